// round 2
// baseline (speedup 1.0000x reference)
#include <cuda_runtime.h>
#include <cstddef>

#define BB      2
#define TT      16384
#define NVOCAB  259
#define CH      128
#define CCH     80
#define NLAYERS 24
#define NFC1    512
#define TILE_T  64

// ---------------- scratch (static device arrays; no allocation) ----------------
__device__ float g_h0[BB * CH * TT];      // 16.8 MB
__device__ float g_h1[BB * CH * TT];      // 16.8 MB
__device__ float g_upA[BB * CCH * TT];    // 10.5 MB
__device__ float g_upB[BB * CCH * TT];    // 10.5 MB
__device__ float g_fc1[BB * TT * NFC1];   // 67 MB

// ---------------- embedding + encoder: h0[b,o,t] = relu(sum_c emb[x[b,t],c]*enc_w[o,c] + enc_b[o])
__global__ void k_embed(const int* __restrict__ x, const float* __restrict__ emb,
                        const float* __restrict__ enc_w, const float* __restrict__ enc_b,
                        float* __restrict__ hout)
{
    extern __shared__ float sm[];
    float* sh_e = sm;            // [c][t] pitch 65  (128*65)
    float* sh_w = sm + CH * 65;  // [o][c]           (128*128)
    int tid = threadIdx.x;
    int t0 = blockIdx.x * TILE_T;
    int b  = blockIdx.y;

    for (int idx = tid; idx < TILE_T * CH; idx += 256) {
        int j = idx >> 7, c = idx & 127;
        int id = x[b * TT + t0 + j];
        sh_e[c * 65 + j] = emb[id * CH + c];
    }
    for (int idx = tid; idx < CH * CH; idx += 256)
        sh_w[idx] = enc_w[idx];
    __syncthreads();

    int tx = tid & 15, ty = tid >> 4;
    int tb = tx * 4, ob = ty * 8;
    float acc[8][4];
#pragma unroll
    for (int oo = 0; oo < 8; oo++)
#pragma unroll
        for (int tt = 0; tt < 4; tt++) acc[oo][tt] = 0.f;

    for (int c = 0; c < CH; c++) {
        float ev[4];
#pragma unroll
        for (int tt = 0; tt < 4; tt++) ev[tt] = sh_e[c * 65 + tb + tt];
#pragma unroll
        for (int oo = 0; oo < 8; oo++) {
            float w = sh_w[(ob + oo) * CH + c];
#pragma unroll
            for (int tt = 0; tt < 4; tt++) acc[oo][tt] += w * ev[tt];
        }
    }
#pragma unroll
    for (int oo = 0; oo < 8; oo++) {
        float bv = enc_b[ob + oo];
#pragma unroll
        for (int tt = 0; tt < 4; tt++)
            hout[(b * CH + ob + oo) * TT + t0 + tb + tt] = fmaxf(acc[oo][tt] + bv, 0.f);
    }
}

// ---------------- upsample stage: out[b,p,q] = relu(b_s + sum_{dh} W[1-dh][q%4] * in[b,p+dh,q/4])
__global__ void k_up(const float* __restrict__ in, float* __restrict__ out, int Win,
                     const float* __restrict__ ups_w, const float* __restrict__ ups_b, int stage)
{
    int Wout = Win * 4;
    int total = BB * CCH * Wout;
    int idx = blockIdx.x * blockDim.x + threadIdx.x;
    if (idx >= total) return;
    int q = idx % Wout;
    int rem = idx / Wout;
    int p = rem % CCH;
    int b = rem / CCH;
    int r = q & 3, m = q >> 2;
    const float* w = ups_w + stage * 12;
    float v = ups_b[stage];
    if (p - 1 >= 0)  v += w[8 + r] * in[(b * CCH + p - 1) * Win + m];  // dh=-1 -> row 2
    v += w[4 + r] * in[(b * CCH + p) * Win + m];                       // dh= 0 -> row 1
    if (p + 1 < CCH) v += w[0 + r] * in[(b * CCH + p + 1) * Win + m];  // dh=+1 -> row 0
    out[idx] = fmaxf(v, 0.f);
}

// ---------------- one residual conv layer:
// hout = relu( relu(dilconv(hin)+cb) + cond_w@cu + cond_b + hin )
__global__ void k_conv(const float* __restrict__ hin, float* __restrict__ hout,
                       const float* __restrict__ conv_w, const float* __restrict__ conv_b,
                       const float* __restrict__ cond_w, const float* __restrict__ cond_b,
                       const float* __restrict__ cu, int l, int d)
{
    extern __shared__ float sm[];
    int W = TILE_T + 2 * d;
    int HP = W + 1;
    float* sh_h  = sm;                       // [i][j] pitch HP   (128*HP)
    float* sh_w  = sm + CH * HP;             // [il][o][k]        (32*128*3)
    float* sh_cu = sh_w + 32 * CH * 3;       // [cc][j] pitch 65  (80*65)
    float* sh_cw = sh_cu + CCH * 65;         // [o][cc]           (128*80)
    int tid = threadIdx.x;
    int t0 = blockIdx.x * TILE_T;
    int b = blockIdx.y;

    {   // h tile, left-zero-padded by 2d
        int j = tid & 127;
        int ih = tid >> 7;   // 0..1
        for (int i0 = 0; i0 < CH; i0 += 2) {
            int i = i0 + ih;
            if (j < W) {
                int t = t0 - 2 * d + j;
                sh_h[i * HP + j] = (t >= 0) ? hin[(b * CH + i) * TT + t] : 0.f;
            }
        }
    }
    {   // cu tile
        int j = tid & 63;
        int ic = tid >> 6;   // 0..3
        for (int c0 = 0; c0 < CCH; c0 += 4) {
            int cc = c0 + ic;
            sh_cu[cc * 65 + j] = cu[(b * CCH + cc) * TT + t0 + j];
        }
    }
    {   // cond weights (contiguous)
        const float* cw = cond_w + l * CH * CCH;
        for (int idx = tid; idx < CH * CCH; idx += 256) sh_cw[idx] = cw[idx];
    }

    int tx = tid & 15, ty = tid >> 4;
    int tb = tx * 4, ob = ty * 8;
    float acc[8][4];
#pragma unroll
    for (int oo = 0; oo < 8; oo++)
#pragma unroll
        for (int tt = 0; tt < 4; tt++) acc[oo][tt] = 0.f;

    const float* wbase = conv_w + (size_t)l * CH * CH * 3;
    for (int i0 = 0; i0 < CH; i0 += 32) {
        __syncthreads();
        for (int idx = tid; idx < 32 * CH * 3; idx += 256) {
            int o = idx / 96;
            int r = idx - o * 96;          // r = il*3 + k
            int il = r / 3;
            int k  = r - il * 3;
            sh_w[il * 384 + o * 3 + k] = wbase[o * 384 + i0 * 3 + r];
        }
        __syncthreads();
#pragma unroll 4
        for (int il = 0; il < 32; il++) {
            const float* hr = sh_h + (i0 + il) * HP + tb;
            float hv0[4], hv1[4], hv2[4];
#pragma unroll
            for (int tt = 0; tt < 4; tt++) {
                hv0[tt] = hr[tt];
                hv1[tt] = hr[d + tt];
                hv2[tt] = hr[2 * d + tt];
            }
            const float* wr = sh_w + il * 384 + ob * 3;
#pragma unroll
            for (int oo = 0; oo < 8; oo++) {
                float w0 = wr[oo * 3 + 0], w1 = wr[oo * 3 + 1], w2 = wr[oo * 3 + 2];
#pragma unroll
                for (int tt = 0; tt < 4; tt++)
                    acc[oo][tt] += w0 * hv0[tt] + w1 * hv1[tt] + w2 * hv2[tt];
            }
        }
    }

    // inner relu: y = relu(conv + conv_b)
#pragma unroll
    for (int oo = 0; oo < 8; oo++) {
        float cb = conv_b[l * CH + ob + oo];
#pragma unroll
        for (int tt = 0; tt < 4; tt++) acc[oo][tt] = fmaxf(acc[oo][tt] + cb, 0.f);
    }
    // accumulate cond into same registers
    for (int cc = 0; cc < CCH; cc++) {
        float cv[4];
#pragma unroll
        for (int tt = 0; tt < 4; tt++) cv[tt] = sh_cu[cc * 65 + tb + tt];
#pragma unroll
        for (int oo = 0; oo < 8; oo++) {
            float w = sh_cw[(ob + oo) * CCH + cc];
#pragma unroll
            for (int tt = 0; tt < 4; tt++) acc[oo][tt] += w * cv[tt];
        }
    }
    // + cond_b + residual, outer relu
#pragma unroll
    for (int oo = 0; oo < 8; oo++) {
        int o = ob + oo;
        float cb2 = cond_b[l * CH + o];
#pragma unroll
        for (int tt = 0; tt < 4; tt++) {
            int tl = tb + tt;
            float v = acc[oo][tt] + cb2 + sh_h[o * HP + 2 * d + tl];
            hout[(b * CH + o) * TT + t0 + tl] = fmaxf(v, 0.f);
        }
    }
}

// ---------------- fc1: h1[b,t,f] = relu(sum_c h[b,c,t]*fc1_w[f,c] + b[f])
__global__ void k_fc1(const float* __restrict__ hin, const float* __restrict__ w,
                      const float* __restrict__ bias, float* __restrict__ out)
{
    extern __shared__ float sm[];
    float* sh_in = sm;            // [c][t] pitch 65 (128*65)
    float* sh_w  = sm + CH * 65;  // [f][c]          (128*128)
    int tid = threadIdx.x;
    int t0 = blockIdx.x * TILE_T;
    int f0 = blockIdx.y * 128;
    int b  = blockIdx.z;

    {
        int j = tid & 63, ic = tid >> 6;
        for (int c0 = 0; c0 < CH; c0 += 4) {
            int c = c0 + ic;
            sh_in[c * 65 + j] = hin[(b * CH + c) * TT + t0 + j];
        }
    }
    for (int idx = tid; idx < 128 * CH; idx += 256) sh_w[idx] = w[f0 * CH + idx];
    __syncthreads();

    int tx = tid & 15, ty = tid >> 4;
    int tb = tx * 4, ob = ty * 8;
    float acc[8][4];
#pragma unroll
    for (int oo = 0; oo < 8; oo++)
#pragma unroll
        for (int tt = 0; tt < 4; tt++) acc[oo][tt] = 0.f;

    for (int c = 0; c < CH; c++) {
        float iv[4];
#pragma unroll
        for (int tt = 0; tt < 4; tt++) iv[tt] = sh_in[c * 65 + tb + tt];
#pragma unroll
        for (int oo = 0; oo < 8; oo++) {
            float wv = sh_w[(ob + oo) * CH + c];
#pragma unroll
            for (int tt = 0; tt < 4; tt++) acc[oo][tt] += wv * iv[tt];
        }
    }
#pragma unroll
    for (int oo = 0; oo < 8; oo++) {
        float bv = bias[f0 + ob + oo];
#pragma unroll
        for (int tt = 0; tt < 4; tt++)
            out[((size_t)(b * TT + t0 + tb + tt)) * NFC1 + f0 + ob + oo] =
                fmaxf(acc[oo][tt] + bv, 0.f);
    }
}

// ---------------- fc2: out[b,t,o] = sum_f h1[b,t,f]*fc2_w[o,f] + b[o], drop t = T-1
__global__ void k_fc2(const float* __restrict__ h1, const float* __restrict__ w,
                      const float* __restrict__ bias, float* __restrict__ out)
{
    extern __shared__ float sm[];
    float* sh_in = sm;            // [f][t] pitch 65 (128*65)
    float* sh_w  = sm + 128 * 65; // [o][f]          (64*128)
    int tid = threadIdx.x;
    int t0 = blockIdx.x * TILE_T;
    int o0 = blockIdx.y * 64;
    int b  = blockIdx.z;

    int tx = tid & 15, ty = tid >> 4;
    int tb = tx * 4;
    float acc[4][4];
#pragma unroll
    for (int oo = 0; oo < 4; oo++)
#pragma unroll
        for (int tt = 0; tt < 4; tt++) acc[oo][tt] = 0.f;

    for (int f0 = 0; f0 < NFC1; f0 += 128) {
        __syncthreads();
        {
            int fl = tid & 127, jh = tid >> 7;
            for (int j0 = 0; j0 < TILE_T; j0 += 2) {
                int j = j0 + jh;
                sh_in[fl * 65 + j] = h1[((size_t)(b * TT + t0 + j)) * NFC1 + f0 + fl];
            }
        }
        for (int idx = tid; idx < 64 * 128; idx += 256) {
            int ol = idx >> 7, fl = idx & 127;
            int o = o0 + ol;
            sh_w[idx] = (o < NVOCAB) ? w[(size_t)o * NFC1 + f0 + fl] : 0.f;
        }
        __syncthreads();
        for (int fl = 0; fl < 128; fl++) {
            float iv[4];
#pragma unroll
            for (int tt = 0; tt < 4; tt++) iv[tt] = sh_in[fl * 65 + tb + tt];
#pragma unroll
            for (int oo = 0; oo < 4; oo++) {
                float wv = sh_w[(ty * 4 + oo) * 128 + fl];
#pragma unroll
                for (int tt = 0; tt < 4; tt++) acc[oo][tt] += wv * iv[tt];
            }
        }
    }
#pragma unroll
    for (int oo = 0; oo < 4; oo++) {
        int o = o0 + ty * 4 + oo;
        if (o < NVOCAB) {
            float bv = bias[o];
#pragma unroll
            for (int tt = 0; tt < 4; tt++) {
                int t = t0 + tb + tt;
                if (t < TT - 1)
                    out[((size_t)b * (TT - 1) + t) * NVOCAB + o] = acc[oo][tt] + bv;
            }
        }
    }
}

// ---------------- host ----------------
extern "C" void kernel_launch(void* const* d_in, const int* in_sizes, int n_in,
                              void* d_out, int out_size)
{
    (void)in_sizes; (void)n_in; (void)out_size;
    const int*   x      = (const int*)d_in[0];
    const float* c      = (const float*)d_in[1];
    const float* emb    = (const float*)d_in[2];
    const float* enc_w  = (const float*)d_in[3];
    const float* enc_b  = (const float*)d_in[4];
    const float* conv_w = (const float*)d_in[5];
    const float* conv_b = (const float*)d_in[6];
    const float* cond_w = (const float*)d_in[7];
    const float* cond_b = (const float*)d_in[8];
    const float* fc1_w  = (const float*)d_in[9];
    const float* fc1_b  = (const float*)d_in[10];
    const float* fc2_w  = (const float*)d_in[11];
    const float* fc2_b  = (const float*)d_in[12];
    const float* ups_w  = (const float*)d_in[13];
    const float* ups_b  = (const float*)d_in[14];
    float* out = (float*)d_out;

    void *pH0, *pH1, *pA, *pB, *pF;
    cudaGetSymbolAddress(&pH0, g_h0);
    cudaGetSymbolAddress(&pH1, g_h1);
    cudaGetSymbolAddress(&pA, g_upA);
    cudaGetSymbolAddress(&pB, g_upB);
    cudaGetSymbolAddress(&pF, g_fc1);
    float* h0 = (float*)pH0;
    float* h1b = (float*)pH1;
    float* ua = (float*)pA;
    float* ub = (float*)pB;
    float* f1 = (float*)pF;

    const int SMEM_EMBED = (CH * 65 + CH * CH) * 4;                       // 98816
    const int SMEM_FC1   = SMEM_EMBED;
    const int SMEM_FC2   = (128 * 65 + 64 * 128) * 4;                     // 66048
    const int SMEM_CONV_MAX = (CH * (TILE_T + 64 + 1) + 32 * CH * 3 + CCH * 65 + CH * CCH) * 4; // 176960

    cudaFuncSetAttribute(k_embed, cudaFuncAttributeMaxDynamicSharedMemorySize, SMEM_EMBED);
    cudaFuncSetAttribute(k_conv,  cudaFuncAttributeMaxDynamicSharedMemorySize, SMEM_CONV_MAX);
    cudaFuncSetAttribute(k_fc1,   cudaFuncAttributeMaxDynamicSharedMemorySize, SMEM_FC1);
    cudaFuncSetAttribute(k_fc2,   cudaFuncAttributeMaxDynamicSharedMemorySize, SMEM_FC2);

    // 1) embedding + encoder
    k_embed<<<dim3(TT / TILE_T, BB), 256, SMEM_EMBED>>>(x, emb, enc_w, enc_b, h0);

    // 2) upsample chain: c -> ua -> ub -> ua -> ub  (cu = ub)
    {
        int Win = 64;
        const float* uin = c;
        float* bufs[2] = { ua, ub };
        for (int s = 0; s < 4; s++) {
            int total = BB * CCH * Win * 4;
            float* uout = bufs[s & 1];
            k_up<<<(total + 255) / 256, 256>>>(uin, uout, Win, ups_w, ups_b, s);
            uin = uout;
            Win *= 4;
        }
    }

    // 3) 24 residual dilated-conv layers (ping-pong h0/h1)
    float* hin = h0;
    float* hout = h1b;
    for (int l = 0; l < NLAYERS; l++) {
        int d = 1 << (l % 6);
        size_t smem = (size_t)(CH * (TILE_T + 2 * d + 1) + 32 * CH * 3 + CCH * 65 + CH * CCH) * 4;
        k_conv<<<dim3(TT / TILE_T, BB), 256, smem>>>(hin, hout, conv_w, conv_b,
                                                     cond_w, cond_b, ub, l, d);
        float* tmp = hin; hin = hout; hout = tmp;
    }
    // 24 swaps (even) -> result back in h0 (== hin)

    // 4) fc1 -> fc2
    k_fc1<<<dim3(TT / TILE_T, NFC1 / 128, BB), 256, SMEM_FC1>>>(hin, fc1_w, fc1_b, f1);
    k_fc2<<<dim3(TT / TILE_T, 5, BB), 256, SMEM_FC2>>>(f1, fc2_w, fc2_b, out);
}

// round 3
// speedup vs baseline: 1.0015x; 1.0015x over previous
#include <cuda_runtime.h>
#include <cstddef>

#define BB      2
#define TT      16384
#define NVOCAB  259
#define CH      128
#define CCH     80
#define NLAYERS 24
#define NFC1    512
#define TILE_T  64

// ---------------- scratch (static device arrays; no allocation) ----------------
__device__ float g_h0[BB * CH * TT];      // 16.8 MB
__device__ float g_h1[BB * CH * TT];      // 16.8 MB
__device__ float g_upA[BB * CCH * TT];    // 10.5 MB
__device__ float g_upB[BB * CCH * TT];    // 10.5 MB
__device__ float g_fc1[BB * TT * NFC1];   // 67 MB

// ---------------- embedding + encoder: h0[b,o,t] = relu(sum_c emb[x[b,t],c]*enc_w[o,c] + enc_b[o])
__global__ void k_embed(const int* __restrict__ x, const float* __restrict__ emb,
                        const float* __restrict__ enc_w, const float* __restrict__ enc_b,
                        float* __restrict__ hout)
{
    extern __shared__ float sm[];
    float* sh_e = sm;            // [c][t] pitch 65  (128*65)
    float* sh_w = sm + CH * 65;  // [o][c]           (128*128)
    int tid = threadIdx.x;
    int t0 = blockIdx.x * TILE_T;
    int b  = blockIdx.y;

    for (int idx = tid; idx < TILE_T * CH; idx += 256) {
        int j = idx >> 7, c = idx & 127;
        int id = x[b * TT + t0 + j];
        sh_e[c * 65 + j] = emb[id * CH + c];
    }
    for (int idx = tid; idx < CH * CH; idx += 256)
        sh_w[idx] = enc_w[idx];
    __syncthreads();

    int tx = tid & 15, ty = tid >> 4;
    int tb = tx * 4, ob = ty * 8;
    float acc[8][4];
#pragma unroll
    for (int oo = 0; oo < 8; oo++)
#pragma unroll
        for (int tt = 0; tt < 4; tt++) acc[oo][tt] = 0.f;

    for (int c = 0; c < CH; c++) {
        float ev[4];
#pragma unroll
        for (int tt = 0; tt < 4; tt++) ev[tt] = sh_e[c * 65 + tb + tt];
#pragma unroll
        for (int oo = 0; oo < 8; oo++) {
            float w = sh_w[(ob + oo) * CH + c];
#pragma unroll
            for (int tt = 0; tt < 4; tt++) acc[oo][tt] += w * ev[tt];
        }
    }
#pragma unroll
    for (int oo = 0; oo < 8; oo++) {
        float bv = enc_b[ob + oo];
#pragma unroll
        for (int tt = 0; tt < 4; tt++)
            hout[(b * CH + ob + oo) * TT + t0 + tb + tt] = fmaxf(acc[oo][tt] + bv, 0.f);
    }
}

// ---------------- upsample stage: out[b,p,q] = relu(b_s + sum_{dh} W[1-dh][q%4] * in[b,p+dh,q/4])
__global__ void k_up(const float* __restrict__ in, float* __restrict__ out, int Win,
                     const float* __restrict__ ups_w, const float* __restrict__ ups_b, int stage)
{
    int Wout = Win * 4;
    int total = BB * CCH * Wout;
    int idx = blockIdx.x * blockDim.x + threadIdx.x;
    if (idx >= total) return;
    int q = idx % Wout;
    int rem = idx / Wout;
    int p = rem % CCH;
    int b = rem / CCH;
    int r = q & 3, m = q >> 2;
    const float* w = ups_w + stage * 12;
    float v = ups_b[stage];
    if (p - 1 >= 0)  v += w[8 + r] * in[(b * CCH + p - 1) * Win + m];  // dh=-1 -> row 2
    v += w[4 + r] * in[(b * CCH + p) * Win + m];                       // dh= 0 -> row 1
    if (p + 1 < CCH) v += w[0 + r] * in[(b * CCH + p + 1) * Win + m];  // dh=+1 -> row 0
    out[idx] = fmaxf(v, 0.f);
}

// ---------------- one residual conv layer:
// hout = relu( relu(dilconv(hin)+cb) + cond_w@cu + cond_b + hin )
__global__ void k_conv(const float* __restrict__ hin, float* __restrict__ hout,
                       const float* __restrict__ conv_w, const float* __restrict__ conv_b,
                       const float* __restrict__ cond_w, const float* __restrict__ cond_b,
                       const float* __restrict__ cu, int l, int d)
{
    extern __shared__ float sm[];
    int W = TILE_T + 2 * d;
    int HP = W + 1;
    float* sh_h  = sm;                       // [i][j] pitch HP   (128*HP)
    float* sh_w  = sm + CH * HP;             // [il][o][k]        (32*128*3)
    float* sh_cu = sh_w + 32 * CH * 3;       // [cc][j] pitch 65  (80*65)
    float* sh_cw = sh_cu + CCH * 65;         // [o][cc]           (128*80)
    int tid = threadIdx.x;
    int t0 = blockIdx.x * TILE_T;
    int b = blockIdx.y;

    {   // h tile, left-zero-padded by 2d
        int j = tid & 127;
        int ih = tid >> 7;   // 0..1
        for (int i0 = 0; i0 < CH; i0 += 2) {
            int i = i0 + ih;
            if (j < W) {
                int t = t0 - 2 * d + j;
                sh_h[i * HP + j] = (t >= 0) ? hin[(b * CH + i) * TT + t] : 0.f;
            }
        }
    }
    {   // cu tile
        int j = tid & 63;
        int ic = tid >> 6;   // 0..3
        for (int c0 = 0; c0 < CCH; c0 += 4) {
            int cc = c0 + ic;
            sh_cu[cc * 65 + j] = cu[(b * CCH + cc) * TT + t0 + j];
        }
    }
    {   // cond weights (contiguous)
        const float* cw = cond_w + l * CH * CCH;
        for (int idx = tid; idx < CH * CCH; idx += 256) sh_cw[idx] = cw[idx];
    }

    int tx = tid & 15, ty = tid >> 4;
    int tb = tx * 4, ob = ty * 8;
    float acc[8][4];
#pragma unroll
    for (int oo = 0; oo < 8; oo++)
#pragma unroll
        for (int tt = 0; tt < 4; tt++) acc[oo][tt] = 0.f;

    const float* wbase = conv_w + (size_t)l * CH * CH * 3;
    for (int i0 = 0; i0 < CH; i0 += 32) {
        __syncthreads();
        for (int idx = tid; idx < 32 * CH * 3; idx += 256) {
            int o = idx / 96;
            int r = idx - o * 96;          // r = il*3 + k
            int il = r / 3;
            int k  = r - il * 3;
            sh_w[il * 384 + o * 3 + k] = wbase[o * 384 + i0 * 3 + r];
        }
        __syncthreads();
#pragma unroll 4
        for (int il = 0; il < 32; il++) {
            const float* hr = sh_h + (i0 + il) * HP + tb;
            float hv0[4], hv1[4], hv2[4];
#pragma unroll
            for (int tt = 0; tt < 4; tt++) {
                hv0[tt] = hr[tt];
                hv1[tt] = hr[d + tt];
                hv2[tt] = hr[2 * d + tt];
            }
            const float* wr = sh_w + il * 384 + ob * 3;
#pragma unroll
            for (int oo = 0; oo < 8; oo++) {
                float w0 = wr[oo * 3 + 0], w1 = wr[oo * 3 + 1], w2 = wr[oo * 3 + 2];
#pragma unroll
                for (int tt = 0; tt < 4; tt++)
                    acc[oo][tt] += w0 * hv0[tt] + w1 * hv1[tt] + w2 * hv2[tt];
            }
        }
    }

    // inner relu: y = relu(conv + conv_b)
#pragma unroll
    for (int oo = 0; oo < 8; oo++) {
        float cb = conv_b[l * CH + ob + oo];
#pragma unroll
        for (int tt = 0; tt < 4; tt++) acc[oo][tt] = fmaxf(acc[oo][tt] + cb, 0.f);
    }
    // accumulate cond into same registers
    for (int cc = 0; cc < CCH; cc++) {
        float cv[4];
#pragma unroll
        for (int tt = 0; tt < 4; tt++) cv[tt] = sh_cu[cc * 65 + tb + tt];
#pragma unroll
        for (int oo = 0; oo < 8; oo++) {
            float w = sh_cw[(ob + oo) * CCH + cc];
#pragma unroll
            for (int tt = 0; tt < 4; tt++) acc[oo][tt] += w * cv[tt];
        }
    }
    // + cond_b + residual, outer relu
#pragma unroll
    for (int oo = 0; oo < 8; oo++) {
        int o = ob + oo;
        float cb2 = cond_b[l * CH + o];
#pragma unroll
        for (int tt = 0; tt < 4; tt++) {
            int tl = tb + tt;
            float v = acc[oo][tt] + cb2 + sh_h[o * HP + 2 * d + tl];
            hout[(b * CH + o) * TT + t0 + tl] = fmaxf(v, 0.f);
        }
    }
}

// ---------------- fc1: h1[b,t,f] = relu(sum_c h[b,c,t]*fc1_w[f,c] + b[f])
__global__ void k_fc1(const float* __restrict__ hin, const float* __restrict__ w,
                      const float* __restrict__ bias, float* __restrict__ out)
{
    extern __shared__ float sm[];
    float* sh_in = sm;            // [c][t] pitch 65 (128*65)
    float* sh_w  = sm + CH * 65;  // [f][c]          (128*128)
    int tid = threadIdx.x;
    int t0 = blockIdx.x * TILE_T;
    int f0 = blockIdx.y * 128;
    int b  = blockIdx.z;

    {
        int j = tid & 63, ic = tid >> 6;
        for (int c0 = 0; c0 < CH; c0 += 4) {
            int c = c0 + ic;
            sh_in[c * 65 + j] = hin[(b * CH + c) * TT + t0 + j];
        }
    }
    for (int idx = tid; idx < 128 * CH; idx += 256) sh_w[idx] = w[f0 * CH + idx];
    __syncthreads();

    int tx = tid & 15, ty = tid >> 4;
    int tb = tx * 4, ob = ty * 8;
    float acc[8][4];
#pragma unroll
    for (int oo = 0; oo < 8; oo++)
#pragma unroll
        for (int tt = 0; tt < 4; tt++) acc[oo][tt] = 0.f;

    for (int c = 0; c < CH; c++) {
        float iv[4];
#pragma unroll
        for (int tt = 0; tt < 4; tt++) iv[tt] = sh_in[c * 65 + tb + tt];
#pragma unroll
        for (int oo = 0; oo < 8; oo++) {
            float wv = sh_w[(ob + oo) * CH + c];
#pragma unroll
            for (int tt = 0; tt < 4; tt++) acc[oo][tt] += wv * iv[tt];
        }
    }
#pragma unroll
    for (int oo = 0; oo < 8; oo++) {
        float bv = bias[f0 + ob + oo];
#pragma unroll
        for (int tt = 0; tt < 4; tt++)
            out[((size_t)(b * TT + t0 + tb + tt)) * NFC1 + f0 + ob + oo] =
                fmaxf(acc[oo][tt] + bv, 0.f);
    }
}

// ---------------- fc2: out[b,t,o] = sum_f h1[b,t,f]*fc2_w[o,f] + b[o], drop t = T-1
__global__ void k_fc2(const float* __restrict__ h1, const float* __restrict__ w,
                      const float* __restrict__ bias, float* __restrict__ out)
{
    extern __shared__ float sm[];
    float* sh_in = sm;            // [f][t] pitch 65 (128*65)
    float* sh_w  = sm + 128 * 65; // [o][f]          (64*128)
    int tid = threadIdx.x;
    int t0 = blockIdx.x * TILE_T;
    int o0 = blockIdx.y * 64;
    int b  = blockIdx.z;

    int tx = tid & 15, ty = tid >> 4;
    int tb = tx * 4;
    float acc[4][4];
#pragma unroll
    for (int oo = 0; oo < 4; oo++)
#pragma unroll
        for (int tt = 0; tt < 4; tt++) acc[oo][tt] = 0.f;

    for (int f0 = 0; f0 < NFC1; f0 += 128) {
        __syncthreads();
        {
            int fl = tid & 127, jh = tid >> 7;
            for (int j0 = 0; j0 < TILE_T; j0 += 2) {
                int j = j0 + jh;
                sh_in[fl * 65 + j] = h1[((size_t)(b * TT + t0 + j)) * NFC1 + f0 + fl];
            }
        }
        for (int idx = tid; idx < 64 * 128; idx += 256) {
            int ol = idx >> 7, fl = idx & 127;
            int o = o0 + ol;
            sh_w[idx] = (o < NVOCAB) ? w[(size_t)o * NFC1 + f0 + fl] : 0.f;
        }
        __syncthreads();
        for (int fl = 0; fl < 128; fl++) {
            float iv[4];
#pragma unroll
            for (int tt = 0; tt < 4; tt++) iv[tt] = sh_in[fl * 65 + tb + tt];
#pragma unroll
            for (int oo = 0; oo < 4; oo++) {
                float wv = sh_w[(ty * 4 + oo) * 128 + fl];
#pragma unroll
                for (int tt = 0; tt < 4; tt++) acc[oo][tt] += wv * iv[tt];
            }
        }
    }
#pragma unroll
    for (int oo = 0; oo < 4; oo++) {
        int o = o0 + ty * 4 + oo;
        if (o < NVOCAB) {
            float bv = bias[o];
#pragma unroll
            for (int tt = 0; tt < 4; tt++) {
                int t = t0 + tb + tt;
                if (t < TT - 1)
                    out[((size_t)b * (TT - 1) + t) * NVOCAB + o] = acc[oo][tt] + bv;
            }
        }
    }
}

// ---------------- host ----------------
extern "C" void kernel_launch(void* const* d_in, const int* in_sizes, int n_in,
                              void* d_out, int out_size)
{
    (void)in_sizes; (void)n_in; (void)out_size;
    const int*   x      = (const int*)d_in[0];
    const float* c      = (const float*)d_in[1];
    const float* emb    = (const float*)d_in[2];
    const float* enc_w  = (const float*)d_in[3];
    const float* enc_b  = (const float*)d_in[4];
    const float* conv_w = (const float*)d_in[5];
    const float* conv_b = (const float*)d_in[6];
    const float* cond_w = (const float*)d_in[7];
    const float* cond_b = (const float*)d_in[8];
    const float* fc1_w  = (const float*)d_in[9];
    const float* fc1_b  = (const float*)d_in[10];
    const float* fc2_w  = (const float*)d_in[11];
    const float* fc2_b  = (const float*)d_in[12];
    const float* ups_w  = (const float*)d_in[13];
    const float* ups_b  = (const float*)d_in[14];
    float* out = (float*)d_out;

    void *pH0, *pH1, *pA, *pB, *pF;
    cudaGetSymbolAddress(&pH0, g_h0);
    cudaGetSymbolAddress(&pH1, g_h1);
    cudaGetSymbolAddress(&pA, g_upA);
    cudaGetSymbolAddress(&pB, g_upB);
    cudaGetSymbolAddress(&pF, g_fc1);
    float* h0 = (float*)pH0;
    float* h1b = (float*)pH1;
    float* ua = (float*)pA;
    float* ub = (float*)pB;
    float* f1 = (float*)pF;

    const int SMEM_EMBED = (CH * 65 + CH * CH) * 4;                       // 98816
    const int SMEM_FC1   = SMEM_EMBED;
    const int SMEM_FC2   = (128 * 65 + 64 * 128) * 4;                     // 66048
    const int SMEM_CONV_MAX = (CH * (TILE_T + 64 + 1) + 32 * CH * 3 + CCH * 65 + CH * CCH) * 4; // 176960

    cudaFuncSetAttribute(k_embed, cudaFuncAttributeMaxDynamicSharedMemorySize, SMEM_EMBED);
    cudaFuncSetAttribute(k_conv,  cudaFuncAttributeMaxDynamicSharedMemorySize, SMEM_CONV_MAX);
    cudaFuncSetAttribute(k_fc1,   cudaFuncAttributeMaxDynamicSharedMemorySize, SMEM_FC1);
    cudaFuncSetAttribute(k_fc2,   cudaFuncAttributeMaxDynamicSharedMemorySize, SMEM_FC2);

    // 1) embedding + encoder
    k_embed<<<dim3(TT / TILE_T, BB), 256, SMEM_EMBED>>>(x, emb, enc_w, enc_b, h0);

    // 2) upsample chain: c -> ua -> ub -> ua -> ub  (cu = ub)
    {
        int Win = 64;
        const float* uin = c;
        float* bufs[2] = { ua, ub };
        for (int s = 0; s < 4; s++) {
            int total = BB * CCH * Win * 4;
            float* uout = bufs[s & 1];
            k_up<<<(total + 255) / 256, 256>>>(uin, uout, Win, ups_w, ups_b, s);
            uin = uout;
            Win *= 4;
        }
    }

    // 3) 24 residual dilated-conv layers (ping-pong h0/h1)
    float* hin = h0;
    float* hout = h1b;
    for (int l = 0; l < NLAYERS; l++) {
        int d = 1 << (l % 6);
        size_t smem = (size_t)(CH * (TILE_T + 2 * d + 1) + 32 * CH * 3 + CCH * 65 + CH * CCH) * 4;
        k_conv<<<dim3(TT / TILE_T, BB), 256, smem>>>(hin, hout, conv_w, conv_b,
                                                     cond_w, cond_b, ub, l, d);
        float* tmp = hin; hin = hout; hout = tmp;
    }
    // 24 swaps (even) -> result back in h0 (== hin)

    // 4) fc1 -> fc2
    k_fc1<<<dim3(TT / TILE_T, NFC1 / 128, BB), 256, SMEM_FC1>>>(hin, fc1_w, fc1_b, f1);
    k_fc2<<<dim3(TT / TILE_T, 5, BB), 256, SMEM_FC2>>>(f1, fc2_w, fc2_b, out);
}